// round 3
// baseline (speedup 1.0000x reference)
#include <cuda_runtime.h>
#include <math.h>

#define BB 32
#define NN 64
#define DD 64

// Scratch (no allocations allowed): 6 att matrices + per-(b,i) aggregates
__device__ float g_att[6 * BB * NN * NN];   // 3 MB
__device__ float g_agg[BB * NN];

__device__ __forceinline__ float ex2_approx(float x) {
    float y; asm("ex2.approx.f32 %0, %1;" : "=f"(y) : "f"(x)); return y;
}
__device__ __forceinline__ float rcp_approx(float x) {
    float y; asm("rcp.approx.f32 %0, %1;" : "=f"(y) : "f"(x)); return y;
}

// ---------------------------------------------------------------------------
// Prologue: per (matrix m, batch b) block computes two key matrices (3->64
// dense) into padded smem, then the 64x64 dot-product att matrix, pre-scaled
// by -scale*log2(e) so the main loop's sigmoid is ex2+rcp with no extra muls.
// m: 0 ajk[j][k], 1 ajl[j][l], 2 alk[l][k], 3 aqj[i][j], 4 aqk[i][k], 5 aql[i][l]
// ---------------------------------------------------------------------------
__global__ void prologue_kernel(const float* __restrict__ pc,
                                const float* __restrict__ Wq,  const float* __restrict__ bq,
                                const float* __restrict__ Wk1, const float* __restrict__ bk1,
                                const float* __restrict__ Wk2, const float* __restrict__ bk2,
                                const float* __restrict__ Wk3, const float* __restrict__ bk3)
{
    __shared__ float L[NN * 65];
    __shared__ float R[NN * 65];
    const int m = blockIdx.x, b = blockIdx.y, tid = threadIdx.x;

    const int lsel[6] = {1, 1, 3, 0, 0, 0};   // 0=q,1=j,2=k,3=l
    const int rsel[6] = {2, 3, 2, 1, 2, 3};
    const float* Ws[4] = {Wq, Wk1, Wk2, Wk3};
    const float* bs[4] = {bq, bk1, bk2, bk3};
    const float* Wl = Ws[lsel[m]]; const float* bl = bs[lsel[m]];
    const float* Wr = Ws[rsel[m]]; const float* br = bs[rsel[m]];
    const float* pcb = pc + b * NN * 3;

    for (int idx = tid; idx < NN * DD; idx += blockDim.x) {
        int n = idx >> 6, d = idx & 63;
        float p0 = pcb[n * 3 + 0], p1 = pcb[n * 3 + 1], p2 = pcb[n * 3 + 2];
        L[n * 65 + d] = fmaf(p0, Wl[d], fmaf(p1, Wl[DD + d], fmaf(p2, Wl[2 * DD + d], bl[d])));
        R[n * 65 + d] = fmaf(p0, Wr[d], fmaf(p1, Wr[DD + d], fmaf(p2, Wr[2 * DD + d], br[d])));
    }
    __syncthreads();

    // -scale * log2(e): sigmoid(E) = 1/(1 + 2^(sum of stored terms))
    const float SC = -0.125f * 1.4426950408889634f;
    float* outm = g_att + (m * BB + b) * NN * NN;
    for (int idx = tid; idx < NN * NN; idx += blockDim.x) {
        int r = idx >> 6, c = idx & 63;
        float s = 0.f;
        #pragma unroll 8
        for (int d = 0; d < DD; ++d) s = fmaf(L[r * 65 + d], R[c * 65 + d], s);
        outm[idx] = SC * s;
    }
}

// ---------------------------------------------------------------------------
// Main kernel: one block per (b, i). 256 threads: k = tid&63 (lane-consecutive
// within warp), jb = tid>>6 (warp-uniform). Each thread: fixed k, 16 j values,
// inner loop over l. cross(d_j,d_k) hoisted per (j,k); det = d_l . cross.
// ---------------------------------------------------------------------------
__global__ void main_kernel(const float* __restrict__ pc)
{
    extern __shared__ float sm[];
    float*  ajk_s = sm;                         // 4096: ajk + aqj[j] + aqk[k]
    float*  bjl_s = sm + 4096;                  // 4096: ajl + aql[l]
    float*  alk_s = sm + 8192;                  // 4096: att_kl transposed [l][k]
    float4* disp4 = (float4*)(sm + 12288);      // 64 float4
    float*  red   = sm + 12288 + 256;           // 256

    const int tid = threadIdx.x;
    const int b = blockIdx.x >> 6, i = blockIdx.x & 63;
    const float* pcb = pc + b * NN * 3;
    const float pix = pcb[i * 3 + 0], piy = pcb[i * 3 + 1], piz = pcb[i * 3 + 2];

    for (int n = tid; n < NN; n += blockDim.x)
        disp4[n] = make_float4(pcb[n * 3 + 0] - pix, pcb[n * 3 + 1] - piy,
                               pcb[n * 3 + 2] - piz, 0.f);

    const float* g_ajk = g_att + (0 * BB + b) * 4096;
    const float* g_ajl = g_att + (1 * BB + b) * 4096;
    const float* g_alk = g_att + (2 * BB + b) * 4096;
    const float* aqj   = g_att + (3 * BB + b) * 4096 + i * NN;
    const float* aqk   = g_att + (4 * BB + b) * 4096 + i * NN;
    const float* aql   = g_att + (5 * BB + b) * 4096 + i * NN;

    for (int idx = tid; idx < 4096; idx += blockDim.x) {
        int r = idx >> 6, c = idx & 63;
        ajk_s[idx] = g_ajk[idx] + aqj[r] + aqk[c];
        bjl_s[idx] = g_ajl[idx] + aql[c];
        alk_s[idx] = g_alk[idx];
    }
    __syncthreads();

    const int k = tid & 63, jb = tid >> 6;
    const float4 dk = disp4[k];
    float acc = 0.f;

    for (int jj = 0; jj < 16; ++jj) {
        const int j = jb * 16 + jj;               // warp-uniform
        const float4 dj = disp4[j];               // broadcast
        // cross(d_j, d_k), reused across all l (triple-product cyclic identity)
        const float crx = dj.y * dk.z - dj.z * dk.y;
        const float cry = dj.z * dk.x - dj.x * dk.z;
        const float crz = dj.x * dk.y - dj.y * dk.x;
        const float c0 = ajk_s[j * NN + k];
        const float* bjlrow = bjl_s + j * NN;
        const float* alkcol = alk_s + k;
        #pragma unroll 8
        for (int l = 0; l < NN; ++l) {
            float e2 = c0 + bjlrow[l] + alkcol[l * NN];   // = -log2e * energy
            float4 dl = disp4[l];                          // uniform -> broadcast
            float det = crx * dl.x + cry * dl.y + crz * dl.z;
            float gate = rcp_approx(1.f + ex2_approx(e2)); // sigmoid(energy)
            acc = fmaf(gate, det * det, acc);
        }
    }

    red[tid] = acc;
    __syncthreads();
    for (int s = 128; s > 0; s >>= 1) {
        if (tid < s) red[tid] += red[tid + s];
        __syncthreads();
    }
    if (tid == 0) g_agg[blockIdx.x] = red[0] * (1.f / 262144.f);
}

// ---------------------------------------------------------------------------
// Final: pool over anchors, 1->32->1 MLP with tanh-approx gelu. One thread/batch.
// ---------------------------------------------------------------------------
__global__ void final_kernel(const float* __restrict__ W1, const float* __restrict__ b1,
                             const float* __restrict__ W2, const float* __restrict__ b2,
                             float* __restrict__ out)
{
    int b = threadIdx.x;
    if (b >= BB) return;
    float p = 0.f;
    for (int i = 0; i < NN; ++i) p += g_agg[b * NN + i];
    p *= (1.f / NN);
    float o = b2[0];
    for (int j = 0; j < 32; ++j) {
        float x = fmaf(p, W1[j], b1[j]);
        float inner = 0.7978845608028654f * (x + 0.044715f * x * x * x);
        float h = 0.5f * x * (1.f + tanhf(inner));
        o = fmaf(h, W2[j], o);
    }
    out[b] = o;
}

extern "C" void kernel_launch(void* const* d_in, const int* in_sizes, int n_in,
                              void* d_out, int out_size)
{
    const float* pc  = (const float*)d_in[0];
    const float* Wq  = (const float*)d_in[1];
    const float* bq  = (const float*)d_in[2];
    const float* Wk1 = (const float*)d_in[3];
    const float* bk1 = (const float*)d_in[4];
    const float* Wk2 = (const float*)d_in[5];
    const float* bk2 = (const float*)d_in[6];
    const float* Wk3 = (const float*)d_in[7];
    const float* bk3 = (const float*)d_in[8];
    const float* W1  = (const float*)d_in[9];
    const float* b1  = (const float*)d_in[10];
    const float* W2  = (const float*)d_in[11];
    const float* b2  = (const float*)d_in[12];
    float* out = (float*)d_out;

    const int MAIN_SMEM = (4096 * 3 + 256 + 256) * (int)sizeof(float);  // 51200 B
    cudaFuncSetAttribute(main_kernel, cudaFuncAttributeMaxDynamicSharedMemorySize, MAIN_SMEM);

    prologue_kernel<<<dim3(6, 32), 256>>>(pc, Wq, bq, Wk1, bk1, Wk2, bk2, Wk3, bk3);
    main_kernel<<<BB * NN, 256, MAIN_SMEM>>>(pc);
    final_kernel<<<1, 32>>>(W1, b1, W2, b2, out);
}